// round 1
// baseline (speedup 1.0000x reference)
#include <cuda_runtime.h>
#include <math.h>

// MoE top-2 of 16, D=1024, F=4096, 4096 tokens, fp32.
// Strategy: gate -> bucket tokens per expert -> grouped GEMM1(+swish) -> grouped GEMM2 -> weighted scatter.
// Only selected experts are computed (8x less FLOPs than the dense reference).

#define D_MODEL 1024
#define N_EXP   16
#define D_FF    4096
#define N_TOK   4096
#define MAXPE   4096          // max tokens per expert (top-2 experts are distinct)
#define TM 64
#define TN 64
#define KC 16

__device__ int   g_count[N_EXP];
__device__ int   g_offset[N_EXP + 1];
__device__ int   g_tok[N_EXP * MAXPE];
__device__ float g_wt[N_EXP * MAXPE];
// H scratch: 8192 selected rows x 4096 = 128 MB fp32
__device__ float g_H[(size_t)2 * N_TOK * D_FF];

// ---------------------------------------------------------------------------
// Reset: zero output (atomic-accumulated later) and routing counters.
// ---------------------------------------------------------------------------
__global__ void reset_kernel(float* __restrict__ out, int out_size) {
    int i = blockIdx.x * blockDim.x + threadIdx.x;
    if (i < N_EXP) g_count[i] = 0;
    for (int j = i; j < out_size; j += gridDim.x * blockDim.x) out[j] = 0.0f;
}

// ---------------------------------------------------------------------------
// Gating: one warp per token. 16 logits via register accumulators + warp
// reduction, then top-2 + softmax, then bucket (expert, token, weight).
// ---------------------------------------------------------------------------
__global__ void gating_kernel(const float* __restrict__ x,
                              const float* __restrict__ Wg) {
    int warp = (blockIdx.x * blockDim.x + threadIdx.x) >> 5;
    int lane = threadIdx.x & 31;
    if (warp >= N_TOK) return;
    const float* xr = x + (size_t)warp * D_MODEL;

    float acc[N_EXP];
#pragma unroll
    for (int e = 0; e < N_EXP; e++) acc[e] = 0.0f;

    for (int d = lane; d < D_MODEL; d += 32) {
        float xv = xr[d];
        const float* wr = Wg + d * N_EXP;
#pragma unroll
        for (int e = 0; e < N_EXP; e++) acc[e] = fmaf(xv, wr[e], acc[e]);
    }
#pragma unroll
    for (int e = 0; e < N_EXP; e++) {
#pragma unroll
        for (int o = 16; o > 0; o >>= 1)
            acc[e] += __shfl_xor_sync(0xffffffffu, acc[e], o);
    }
    if (lane == 0) {
        // top-2 (ties -> lower index, matching jax.lax.top_k)
        int i1 = 0; float v1 = acc[0];
#pragma unroll
        for (int e = 1; e < N_EXP; e++) if (acc[e] > v1) { v1 = acc[e]; i1 = e; }
        int i2 = -1; float v2 = -INFINITY;
#pragma unroll
        for (int e = 0; e < N_EXP; e++)
            if (e != i1 && acc[e] > v2) { v2 = acc[e]; i2 = e; }
        // softmax over {v1, v2}; v1 >= v2
        float e2 = expf(v2 - v1);
        float inv = 1.0f / (1.0f + e2);
        float w1 = inv;
        float w2 = e2 * inv;

        int s1 = atomicAdd(&g_count[i1], 1);
        g_tok[i1 * MAXPE + s1] = warp;
        g_wt [i1 * MAXPE + s1] = w1;
        int s2 = atomicAdd(&g_count[i2], 1);
        g_tok[i2 * MAXPE + s2] = warp;
        g_wt [i2 * MAXPE + s2] = w2;
    }
}

// ---------------------------------------------------------------------------
// Exclusive prefix over 16 expert counts (single thread; trivial).
// ---------------------------------------------------------------------------
__global__ void offsets_kernel() {
    int s = 0;
    for (int e = 0; e < N_EXP; e++) { g_offset[e] = s; s += g_count[e]; }
    g_offset[N_EXP] = s;
}

// ---------------------------------------------------------------------------
// GEMM1: H[row, f] = swish( x[token] @ W1[e] + b1[e] )
// 64x64 tile, 256 threads, 4x4 microtile, K-chunks of 16 via smem.
// ---------------------------------------------------------------------------
__global__ __launch_bounds__(256) void ffn1_kernel(const float* __restrict__ x,
                                                   const float* __restrict__ W1,
                                                   const float* __restrict__ b1) {
    int e   = blockIdx.z;
    int cnt = g_count[e];
    int m0  = blockIdx.y * TM;
    if (m0 >= cnt) return;
    int n0  = blockIdx.x * TN;
    const float* W = W1 + (size_t)e * D_MODEL * D_FF;

    __shared__ __align__(16) float As[KC][TM];
    __shared__ __align__(16) float Bs[KC][TN];

    int tid   = threadIdx.x;
    int a_row = tid >> 2;                 // 0..63
    int a_k4  = (tid & 3) * 4;            // 0,4,8,12
    int slot  = m0 + a_row;
    int tokA  = g_tok[e * MAXPE + ((slot < cnt) ? slot : m0)];
    const float* arow = x + (size_t)tokA * D_MODEL;

    int b_row = tid >> 4;                 // 0..15
    int b_n4  = (tid & 15) * 4;           // 0..60

    int tx = tid & 15, ty = tid >> 4;
    float acc[4][4] = {};

    for (int k0 = 0; k0 < D_MODEL; k0 += KC) {
        float4 av = *reinterpret_cast<const float4*>(arow + k0 + a_k4);
        float4 bv = *reinterpret_cast<const float4*>(
            W + (size_t)(k0 + b_row) * D_FF + n0 + b_n4);
        __syncthreads();
        As[a_k4 + 0][a_row] = av.x;
        As[a_k4 + 1][a_row] = av.y;
        As[a_k4 + 2][a_row] = av.z;
        As[a_k4 + 3][a_row] = av.w;
        *reinterpret_cast<float4*>(&Bs[b_row][b_n4]) = bv;
        __syncthreads();
#pragma unroll
        for (int kk = 0; kk < KC; kk++) {
            float4 a = *reinterpret_cast<const float4*>(&As[kk][ty * 4]);
            float4 b = *reinterpret_cast<const float4*>(&Bs[kk][tx * 4]);
            acc[0][0] = fmaf(a.x, b.x, acc[0][0]);
            acc[0][1] = fmaf(a.x, b.y, acc[0][1]);
            acc[0][2] = fmaf(a.x, b.z, acc[0][2]);
            acc[0][3] = fmaf(a.x, b.w, acc[0][3]);
            acc[1][0] = fmaf(a.y, b.x, acc[1][0]);
            acc[1][1] = fmaf(a.y, b.y, acc[1][1]);
            acc[1][2] = fmaf(a.y, b.z, acc[1][2]);
            acc[1][3] = fmaf(a.y, b.w, acc[1][3]);
            acc[2][0] = fmaf(a.z, b.x, acc[2][0]);
            acc[2][1] = fmaf(a.z, b.y, acc[2][1]);
            acc[2][2] = fmaf(a.z, b.z, acc[2][2]);
            acc[2][3] = fmaf(a.z, b.w, acc[2][3]);
            acc[3][0] = fmaf(a.w, b.x, acc[3][0]);
            acc[3][1] = fmaf(a.w, b.y, acc[3][1]);
            acc[3][2] = fmaf(a.w, b.z, acc[3][2]);
            acc[3][3] = fmaf(a.w, b.w, acc[3][3]);
        }
    }

    int e_off = g_offset[e];
    const float* b1e = b1 + e * D_FF;
#pragma unroll
    for (int i = 0; i < 4; i++) {
        int slot_i = m0 + ty * 4 + i;
        if (slot_i >= cnt) break;
        float* hrow = g_H + (size_t)(e_off + slot_i) * D_FF + n0 + tx * 4;
        float4 o;
        float v0 = acc[i][0] + b1e[n0 + tx * 4 + 0];
        float v1 = acc[i][1] + b1e[n0 + tx * 4 + 1];
        float v2 = acc[i][2] + b1e[n0 + tx * 4 + 2];
        float v3 = acc[i][3] + b1e[n0 + tx * 4 + 3];
        o.x = v0 / (1.0f + __expf(-v0));
        o.y = v1 / (1.0f + __expf(-v1));
        o.z = v2 / (1.0f + __expf(-v2));
        o.w = v3 / (1.0f + __expf(-v3));
        *reinterpret_cast<float4*>(hrow) = o;
    }
}

// ---------------------------------------------------------------------------
// GEMM2: out[token] += wt * ( H[row] @ W2[e] + b2[e] ), atomic scatter.
// ---------------------------------------------------------------------------
__global__ __launch_bounds__(256) void ffn2_kernel(const float* __restrict__ W2,
                                                   const float* __restrict__ b2,
                                                   float* __restrict__ out) {
    int e   = blockIdx.z;
    int cnt = g_count[e];
    int m0  = blockIdx.y * TM;
    if (m0 >= cnt) return;
    int n0  = blockIdx.x * TN;
    const float* W = W2 + (size_t)e * D_FF * D_MODEL;
    int e_off = g_offset[e];

    __shared__ __align__(16) float As[KC][TM];
    __shared__ __align__(16) float Bs[KC][TN];

    int tid   = threadIdx.x;
    int a_row = tid >> 2;
    int a_k4  = (tid & 3) * 4;
    int slot  = m0 + a_row;
    int arow_idx = e_off + ((slot < cnt) ? slot : m0);
    const float* arow = g_H + (size_t)arow_idx * D_FF;

    int b_row = tid >> 4;
    int b_n4  = (tid & 15) * 4;

    int tx = tid & 15, ty = tid >> 4;
    float acc[4][4] = {};

    for (int k0 = 0; k0 < D_FF; k0 += KC) {
        float4 av = *reinterpret_cast<const float4*>(arow + k0 + a_k4);
        float4 bv = *reinterpret_cast<const float4*>(
            W + (size_t)(k0 + b_row) * D_MODEL + n0 + b_n4);
        __syncthreads();
        As[a_k4 + 0][a_row] = av.x;
        As[a_k4 + 1][a_row] = av.y;
        As[a_k4 + 2][a_row] = av.z;
        As[a_k4 + 3][a_row] = av.w;
        *reinterpret_cast<float4*>(&Bs[b_row][b_n4]) = bv;
        __syncthreads();
#pragma unroll
        for (int kk = 0; kk < KC; kk++) {
            float4 a = *reinterpret_cast<const float4*>(&As[kk][ty * 4]);
            float4 b = *reinterpret_cast<const float4*>(&Bs[kk][tx * 4]);
            acc[0][0] = fmaf(a.x, b.x, acc[0][0]);
            acc[0][1] = fmaf(a.x, b.y, acc[0][1]);
            acc[0][2] = fmaf(a.x, b.z, acc[0][2]);
            acc[0][3] = fmaf(a.x, b.w, acc[0][3]);
            acc[1][0] = fmaf(a.y, b.x, acc[1][0]);
            acc[1][1] = fmaf(a.y, b.y, acc[1][1]);
            acc[1][2] = fmaf(a.y, b.z, acc[1][2]);
            acc[1][3] = fmaf(a.y, b.w, acc[1][3]);
            acc[2][0] = fmaf(a.z, b.x, acc[2][0]);
            acc[2][1] = fmaf(a.z, b.y, acc[2][1]);
            acc[2][2] = fmaf(a.z, b.z, acc[2][2]);
            acc[2][3] = fmaf(a.z, b.w, acc[2][3]);
            acc[3][0] = fmaf(a.w, b.x, acc[3][0]);
            acc[3][1] = fmaf(a.w, b.y, acc[3][1]);
            acc[3][2] = fmaf(a.w, b.z, acc[3][2]);
            acc[3][3] = fmaf(a.w, b.w, acc[3][3]);
        }
    }

    const float* b2e = b2 + e * D_MODEL;
#pragma unroll
    for (int i = 0; i < 4; i++) {
        int slot_i = m0 + ty * 4 + i;
        if (slot_i >= cnt) break;
        int tok = g_tok[e * MAXPE + slot_i];
        float w = g_wt[e * MAXPE + slot_i];
        float* orow = out + (size_t)tok * D_MODEL + n0 + tx * 4;
#pragma unroll
        for (int j = 0; j < 4; j++) {
            float v = acc[i][j] + b2e[n0 + tx * 4 + j];
            atomicAdd(&orow[j], w * v);
        }
    }
}

// ---------------------------------------------------------------------------
extern "C" void kernel_launch(void* const* d_in, const int* in_sizes, int n_in,
                              void* d_out, int out_size) {
    const float* x  = (const float*)d_in[0];  // [2,2048,1024]
    const float* W1 = (const float*)d_in[1];  // [16,1024,4096]
    const float* b1 = (const float*)d_in[2];  // [16,4096]
    const float* W2 = (const float*)d_in[3];  // [16,4096,1024]
    const float* b2 = (const float*)d_in[4];  // [16,1024]
    const float* Wg = (const float*)d_in[5];  // [1024,16]
    float* out = (float*)d_out;               // [2,2048,1024]

    reset_kernel<<<4096, 256>>>(out, out_size);
    gating_kernel<<<N_TOK / 8, 256>>>(x, Wg);
    offsets_kernel<<<1, 1>>>();
    ffn1_kernel<<<dim3(D_FF / TN, MAXPE / TM, N_EXP), 256>>>(x, W1, b1);
    ffn2_kernel<<<dim3(D_MODEL / TN, MAXPE / TM, N_EXP), 256>>>(W2, b2, out);
}

// round 5
// speedup vs baseline: 2.4521x; 2.4521x over previous
#include <cuda_runtime.h>
#include <cuda_bf16.h>
#include <cstdint>
#include <math.h>

// MoE top-2/16: gate -> bucket -> grouped HMMA bf16-split GEMM1(+swish) -> grouped GEMM2 -> scatter.
// mma.sync.m16n8k16 (sm_80+ ISA; works with plain sm_103 ptx target -- tcgen05 does NOT).

#define D_MODEL 1024
#define N_EXP   16
#define D_FF    4096
#define N_TOK   4096
#define MAXPE   4096

__device__ int   g_count[N_EXP];
__device__ int   g_offset[N_EXP + 1];
__device__ int   g_tok[N_EXP * MAXPE];
__device__ float g_wt[N_EXP * MAXPE];
__device__ float g_H[(size_t)2 * N_TOK * D_FF];   // 128 MB fp32 scratch

// ---------------------------------------------------------------------------
__device__ __forceinline__ uint32_t smem_to_u32(const void* p) {
    uint32_t a;
    asm("{ .reg .u64 t; cvta.to.shared.u64 t, %1; cvt.u32.u64 %0, t; }" : "=r"(a) : "l"(p));
    return a;
}

#define LDSM_X4(r, a)                                                            \
    asm volatile("ldmatrix.sync.aligned.m8n8.x4.shared.b16 {%0,%1,%2,%3}, [%4];" \
        : "=r"((r)[0]), "=r"((r)[1]), "=r"((r)[2]), "=r"((r)[3]) : "r"(a))

__device__ __forceinline__ void mma_bf16(float* d, const uint32_t* a, const uint32_t* b) {
    asm volatile("mma.sync.aligned.m16n8k16.row.col.f32.bf16.bf16.f32 "
        "{%0,%1,%2,%3}, {%4,%5,%6,%7}, {%8,%9}, {%0,%1,%2,%3};"
        : "+f"(d[0]), "+f"(d[1]), "+f"(d[2]), "+f"(d[3])
        : "r"(a[0]), "r"(a[1]), "r"(a[2]), "r"(a[3]), "r"(b[0]), "r"(b[1]));
}

// Split fp32 pair -> (hi bf16x2, lo bf16x2); a = low half of the pair.
__device__ __forceinline__ void split2(float a, float b, uint32_t& hi, uint32_t& lo) {
    uint32_t h;
    asm("cvt.rn.satfinite.bf16x2.f32 %0, %1, %2;" : "=r"(h) : "f"(b), "f"(a));
    float ah = __uint_as_float(h << 16);
    float bh = __uint_as_float(h & 0xffff0000u);
    float ar = a - ah, br = b - bh;
    uint32_t l;
    asm("cvt.rn.satfinite.bf16x2.f32 %0, %1, %2;" : "=r"(l) : "f"(br), "f"(ar));
    hi = h; lo = l;
}

// ---------------------------------------------------------------------------
// Small kernels: reset, gating, offsets
// ---------------------------------------------------------------------------
__global__ void reset_kernel(float* __restrict__ out, int out_size) {
    int i = blockIdx.x * blockDim.x + threadIdx.x;
    if (i < N_EXP) g_count[i] = 0;
    for (int j = i; j < out_size; j += gridDim.x * blockDim.x) out[j] = 0.0f;
}

__global__ void gating_kernel(const float* __restrict__ x, const float* __restrict__ Wg) {
    int warp = (blockIdx.x * blockDim.x + threadIdx.x) >> 5;
    int lane = threadIdx.x & 31;
    if (warp >= N_TOK) return;
    const float* xr = x + (size_t)warp * D_MODEL;
    float acc[N_EXP];
#pragma unroll
    for (int e = 0; e < N_EXP; e++) acc[e] = 0.0f;
    for (int d = lane; d < D_MODEL; d += 32) {
        float xv = xr[d];
        const float* wr = Wg + d * N_EXP;
#pragma unroll
        for (int e = 0; e < N_EXP; e++) acc[e] = fmaf(xv, wr[e], acc[e]);
    }
#pragma unroll
    for (int e = 0; e < N_EXP; e++) {
#pragma unroll
        for (int o = 16; o > 0; o >>= 1) acc[e] += __shfl_xor_sync(0xffffffffu, acc[e], o);
    }
    if (lane == 0) {
        int i1 = 0; float v1 = acc[0];
#pragma unroll
        for (int e = 1; e < N_EXP; e++) if (acc[e] > v1) { v1 = acc[e]; i1 = e; }
        int i2 = -1; float v2 = -INFINITY;
#pragma unroll
        for (int e = 0; e < N_EXP; e++) if (e != i1 && acc[e] > v2) { v2 = acc[e]; i2 = e; }
        float e2 = expf(v2 - v1);
        float inv = 1.0f / (1.0f + e2);
        int s1 = atomicAdd(&g_count[i1], 1);
        g_tok[i1 * MAXPE + s1] = warp;  g_wt[i1 * MAXPE + s1] = inv;
        int s2 = atomicAdd(&g_count[i2], 1);
        g_tok[i2 * MAXPE + s2] = warp;  g_wt[i2 * MAXPE + s2] = e2 * inv;
    }
}

__global__ void offsets_kernel() {
    int s = 0;
    for (int e = 0; e < N_EXP; e++) { g_offset[e] = s; s += g_count[e]; }
    g_offset[N_EXP] = s;
}

// ---------------------------------------------------------------------------
// Grouped GEMM via mma.sync bf16 hi/lo split (3 MMAs per product).
// Tile: M=128 x N=128, K-chunk=64, 8 warps in 4(M)x2(N) grid, warp tile 32x64.
// smem per stage: A[128 rows][64 k] bf16 (hi, lo) + B[128 n][64 k] bf16 (hi, lo).
// Swizzle: 16B chunk c of row r stored at (c ^ (r&7)) -- conflict-free STS + ldmatrix.
// PHASE 1: H = swish(x @ W1 + b1)   (K=1024, N=4096, A rows gathered by token)
// PHASE 2: out += wt*(H @ W2 + b2)  (K=4096, N=1024, atomic scatter)
// ---------------------------------------------------------------------------
#define AHI_OFF  0
#define ALO_OFF  16384
#define BHI_OFF  32768
#define BLO_OFF  49152
#define STAGE_STRIDE 65536
#define SMEM_BYTES (2 * STAGE_STRIDE)

template <int PHASE>
__global__ __launch_bounds__(256, 1)
void ffn_hmma_kernel(const float* __restrict__ Abase,
                     const float* __restrict__ W,
                     const float* __restrict__ bias,
                     float* __restrict__ out)
{
    constexpr int KTOT = (PHASE == 1) ? D_MODEL : D_FF;
    constexpr int NTOT = (PHASE == 1) ? D_FF : D_MODEL;
    constexpr int LDA  = (PHASE == 1) ? D_MODEL : D_FF;
    constexpr int L    = KTOT / 64;

    const int e   = blockIdx.z;
    const int cnt = g_count[e];
    const int m0  = blockIdx.y * 128;
    if (m0 >= cnt) return;
    const int n0    = blockIdx.x * 128;
    const int e_off = g_offset[e];
    const float* We = W + (size_t)e * KTOT * NTOT;

    extern __shared__ char smem[];
    const uint32_t smem_u = smem_to_u32(smem);
    const int tid  = threadIdx.x;
    const int wid  = tid >> 5;
    const int lane = tid & 31;
    const int wm   = wid >> 1;       // 0..3 -> warp rows wm*32
    const int wn   = wid & 1;        // 0..1 -> warp cols wn*64

    // ---- gmem source pointers for staging ----
    const float* arow[8];
#pragma unroll
    for (int it = 0; it < 8; it++) {
        int m = it * 16 + (tid >> 4);
        int slot = m0 + m; if (slot >= cnt) slot = cnt - 1;
        int r = (PHASE == 1) ? g_tok[e * MAXPE + slot] : (e_off + slot);
        const float* base = (PHASE == 1) ? Abase : (const float*)g_H;
        arow[it] = base + (size_t)r * LDA;
    }
    const int nB = tid & 127;            // B smem row (output column)
    const int kh = tid >> 7;             // which 32-k half this thread loads
    const float* Wcol = We + n0 + nB;

    // ---- ldmatrix lane address components ----
    const int a_row0 = wm * 32 + (lane & 7) + (lane & 8);          // + mb*16
    const int a_kt   = (lane >> 4) & 1;
    const int b_row0 = wn * 64 + (lane & 7) + ((lane & 16) ? 8 : 0); // + np*16
    const int b_kt   = (lane >> 3) & 1;

    float acc[2][8][4];
#pragma unroll
    for (int mb = 0; mb < 2; mb++)
#pragma unroll
        for (int nb = 0; nb < 8; nb++)
#pragma unroll
            for (int q = 0; q < 4; q++) acc[mb][nb][q] = 0.0f;

    // ---- staging lambda-equivalents (macro-ish inline) ----
    auto ldg_chunk = [&](int c, float4* aR, float* bR) {
        const int k0 = c * 64;
#pragma unroll
        for (int it = 0; it < 8; it++)
            aR[it] = *reinterpret_cast<const float4*>(arow[it] + k0 + (tid & 15) * 4);
#pragma unroll
        for (int kb = 0; kb < 4; kb++)
#pragma unroll
            for (int j = 0; j < 8; j++)
                bR[kb * 8 + j] = __ldg(Wcol + (size_t)(k0 + kh * 32 + kb * 8 + j) * NTOT);
    };
    auto sts_chunk = [&](int buf, const float4* aR, const float* bR) {
        char* stage = smem + buf * STAGE_STRIDE;
#pragma unroll
        for (int it = 0; it < 8; it++) {
            int m  = it * 16 + (tid >> 4);
            int cA = (tid & 15) * 8;
            int off = m * 128 + (cA ^ ((m & 7) << 4));
            uint32_t h0, l0, h1, l1;
            split2(aR[it].x, aR[it].y, h0, l0);
            split2(aR[it].z, aR[it].w, h1, l1);
            *reinterpret_cast<uint2*>(stage + AHI_OFF + off) = make_uint2(h0, h1);
            *reinterpret_cast<uint2*>(stage + ALO_OFF + off) = make_uint2(l0, l1);
        }
#pragma unroll
        for (int kb = 0; kb < 4; kb++) {
            int cB = kh * 64 + kb * 16;
            int off = nB * 128 + (cB ^ ((nB & 7) << 4));
            uint32_t h[4], l[4];
#pragma unroll
            for (int p = 0; p < 4; p++)
                split2(bR[kb * 8 + p * 2], bR[kb * 8 + p * 2 + 1], h[p], l[p]);
            *reinterpret_cast<uint4*>(stage + BHI_OFF + off) = make_uint4(h[0], h[1], h[2], h[3]);
            *reinterpret_cast<uint4*>(stage + BLO_OFF + off) = make_uint4(l[0], l[1], l[2], l[3]);
        }
    };

    // ---- preload chunk 0 ----
    {
        float4 aR[8]; float bR[32];
        ldg_chunk(0, aR, bR);
        sts_chunk(0, aR, bR);
    }
    __syncthreads();

    for (int c = 0; c < L; c++) {
        const uint32_t stage_u = smem_u + (c & 1) * STAGE_STRIDE;
        // ---- compute chunk c ----
#pragma unroll
        for (int ks = 0; ks < 4; ks++) {
            uint32_t ah[2][4], al[2][4];
#pragma unroll
            for (int mb = 0; mb < 2; mb++) {
                int row = a_row0 + mb * 16;
                uint32_t off = row * 128 + (((2 * ks + a_kt) ^ (row & 7)) << 4);
                LDSM_X4(ah[mb], stage_u + AHI_OFF + off);
                LDSM_X4(al[mb], stage_u + ALO_OFF + off);
            }
            uint32_t bh[4][4], bl[4][4];
#pragma unroll
            for (int np = 0; np < 4; np++) {
                int row = b_row0 + np * 16;
                uint32_t off = row * 128 + (((2 * ks + b_kt) ^ (row & 7)) << 4);
                LDSM_X4(bh[np], stage_u + BHI_OFF + off);
                LDSM_X4(bl[np], stage_u + BLO_OFF + off);
            }
#pragma unroll
            for (int mb = 0; mb < 2; mb++) {
#pragma unroll
                for (int nb = 0; nb < 8; nb++)
                    mma_bf16(acc[mb][nb], ah[mb], &bh[nb >> 1][(nb & 1) * 2]);
#pragma unroll
                for (int nb = 0; nb < 8; nb++)
                    mma_bf16(acc[mb][nb], ah[mb], &bl[nb >> 1][(nb & 1) * 2]);
#pragma unroll
                for (int nb = 0; nb < 8; nb++)
                    mma_bf16(acc[mb][nb], al[mb], &bh[nb >> 1][(nb & 1) * 2]);
            }
        }
        // ---- stage chunk c+1 ----
        if (c + 1 < L) {
            float4 aR[8]; float bR[32];
            ldg_chunk(c + 1, aR, bR);
            __syncthreads();                 // all warps done computing chunk c
            sts_chunk((c + 1) & 1, aR, bR);
            __syncthreads();                 // staging visible
        }
    }

    // ---- epilogue ----
    const int gp = lane >> 2;        // accumulator row group 0..7
    const int qq = lane & 3;         // column pair index
#pragma unroll
    for (int mb = 0; mb < 2; mb++) {
#pragma unroll
        for (int h = 0; h < 2; h++) {        // row r and r+8 halves of the frag
            int mloc = wm * 32 + mb * 16 + gp + h * 8;
            int slot = m0 + mloc;
            if (slot >= cnt) continue;
            if (PHASE == 1) {
                float* hrow = g_H + (size_t)(e_off + slot) * D_FF;
#pragma unroll
                for (int nb = 0; nb < 8; nb++) {
                    int cidx = n0 + wn * 64 + nb * 8 + qq * 2;
                    float v0 = acc[mb][nb][h * 2 + 0] + __ldg(bias + e * NTOT + cidx + 0);
                    float v1 = acc[mb][nb][h * 2 + 1] + __ldg(bias + e * NTOT + cidx + 1);
                    float2 o;
                    o.x = v0 / (1.0f + __expf(-v0));
                    o.y = v1 / (1.0f + __expf(-v1));
                    *reinterpret_cast<float2*>(hrow + cidx) = o;
                }
            } else {
                int   tok = g_tok[e * MAXPE + slot];
                float w   = g_wt[e * MAXPE + slot];
                float* orow = out + (size_t)tok * D_MODEL;
#pragma unroll
                for (int nb = 0; nb < 8; nb++) {
                    int cidx = n0 + wn * 64 + nb * 8 + qq * 2;
                    float v0 = acc[mb][nb][h * 2 + 0] + __ldg(bias + e * NTOT + cidx + 0);
                    float v1 = acc[mb][nb][h * 2 + 1] + __ldg(bias + e * NTOT + cidx + 1);
                    atomicAdd(orow + cidx + 0, w * v0);
                    atomicAdd(orow + cidx + 1, w * v1);
                }
            }
        }
    }
}

// ---------------------------------------------------------------------------
extern "C" void kernel_launch(void* const* d_in, const int* in_sizes, int n_in,
                              void* d_out, int out_size) {
    const float* x  = (const float*)d_in[0];  // [2,2048,1024]
    const float* W1 = (const float*)d_in[1];  // [16,1024,4096]
    const float* b1 = (const float*)d_in[2];  // [16,4096]
    const float* W2 = (const float*)d_in[3];  // [16,4096,1024]
    const float* b2 = (const float*)d_in[4];  // [16,1024]
    const float* Wg = (const float*)d_in[5];  // [1024,16]
    float* out = (float*)d_out;               // [2,2048,1024]

    cudaFuncSetAttribute(ffn_hmma_kernel<1>, cudaFuncAttributeMaxDynamicSharedMemorySize, SMEM_BYTES);
    cudaFuncSetAttribute(ffn_hmma_kernel<2>, cudaFuncAttributeMaxDynamicSharedMemorySize, SMEM_BYTES);

    reset_kernel<<<4096, 256>>>(out, out_size);
    gating_kernel<<<N_TOK / 8, 256>>>(x, Wg);
    offsets_kernel<<<1, 1>>>();
    ffn_hmma_kernel<1><<<dim3(D_FF / 128, MAXPE / 128, N_EXP), 256, SMEM_BYTES>>>(x, W1, b1, out);
    ffn_hmma_kernel<2><<<dim3(D_MODEL / 128, MAXPE / 128, N_EXP), 256, SMEM_BYTES>>>(nullptr, W2, b2, out);
}

// round 8
// speedup vs baseline: 3.5052x; 1.4295x over previous
#include <cuda_runtime.h>
#include <cuda_fp16.h>
#include <cstdint>
#include <math.h>

// MoE top-2/16: gate -> bucket -> grouped HMMA GEMM1(+swish) -> grouped GEMM2 -> scatter.
// fp16 2-term split (A = hi+lo fp16, B = fp16), mma.sync.m16n8k16.f32.f16.f16.f32.
// R5-validated skeleton: register-staged LDG->STS double buffer + ldmatrix + XOR swizzle.
// Delta vs R5: 1/3 fewer MMAs (2-term), LDG issued ahead of the sync pair to hide DRAM latency.

#define D_MODEL 1024
#define N_EXP   16
#define D_FF    4096
#define N_TOK   4096
#define MAXPE   4096

__device__ int   g_count[N_EXP];
__device__ int   g_offset[N_EXP + 1];
__device__ int   g_tok[N_EXP * MAXPE];
__device__ float g_wt[N_EXP * MAXPE];
__device__ float g_H[(size_t)2 * N_TOK * D_FF];   // 128 MB fp32 scratch

// ---------------------------------------------------------------------------
__device__ __forceinline__ uint32_t smem_to_u32(const void* p) {
    uint32_t a;
    asm("{ .reg .u64 t; cvta.to.shared.u64 t, %1; cvt.u32.u64 %0, t; }" : "=r"(a) : "l"(p));
    return a;
}

#define LDSM_X4(r, a)                                                            \
    asm volatile("ldmatrix.sync.aligned.m8n8.x4.shared.b16 {%0,%1,%2,%3}, [%4];" \
        : "=r"((r)[0]), "=r"((r)[1]), "=r"((r)[2]), "=r"((r)[3]) : "r"(a))

__device__ __forceinline__ void mma_f16(float* d, const uint32_t* a, const uint32_t* b) {
    asm volatile("mma.sync.aligned.m16n8k16.row.col.f32.f16.f16.f32 "
        "{%0,%1,%2,%3}, {%4,%5,%6,%7}, {%8,%9}, {%0,%1,%2,%3};"
        : "+f"(d[0]), "+f"(d[1]), "+f"(d[2]), "+f"(d[3])
        : "r"(a[0]), "r"(a[1]), "r"(a[2]), "r"(a[3]), "r"(b[0]), "r"(b[1]));
}

// pack(a, b) -> f16x2 with a in LOW half, b in HIGH half (memory order [a, b]).
__device__ __forceinline__ uint32_t packf16(float a, float b) {
    uint32_t r;
    asm("cvt.rn.f16x2.f32 %0, %1, %2;" : "=r"(r) : "f"(b), "f"(a));
    return r;
}
// fp16 split: (a,b) -> hi pair + residual pair (a - fp16(a), b - fp16(b)).
__device__ __forceinline__ void split2(float a, float b, uint32_t& hi, uint32_t& lo) {
    uint32_t h = packf16(a, b);
    __half2 hh = *reinterpret_cast<__half2*>(&h);
    float ah = __low2float(hh), bh = __high2float(hh);
    hi = h;
    lo = packf16(a - ah, b - bh);
}

// ---------------------------------------------------------------------------
// reset / gating / offsets (unchanged from R5)
// ---------------------------------------------------------------------------
__global__ void reset_kernel(float* __restrict__ out, int out_size) {
    int i = blockIdx.x * blockDim.x + threadIdx.x;
    if (i < N_EXP) g_count[i] = 0;
    for (int j = i; j < out_size; j += gridDim.x * blockDim.x) out[j] = 0.0f;
}

__global__ void gating_kernel(const float* __restrict__ x, const float* __restrict__ Wg) {
    int warp = (blockIdx.x * blockDim.x + threadIdx.x) >> 5;
    int lane = threadIdx.x & 31;
    if (warp >= N_TOK) return;
    const float* xr = x + (size_t)warp * D_MODEL;
    float acc[N_EXP];
#pragma unroll
    for (int e = 0; e < N_EXP; e++) acc[e] = 0.0f;
    for (int d = lane; d < D_MODEL; d += 32) {
        float xv = xr[d];
        const float* wr = Wg + d * N_EXP;
#pragma unroll
        for (int e = 0; e < N_EXP; e++) acc[e] = fmaf(xv, wr[e], acc[e]);
    }
#pragma unroll
    for (int e = 0; e < N_EXP; e++) {
#pragma unroll
        for (int o = 16; o > 0; o >>= 1) acc[e] += __shfl_xor_sync(0xffffffffu, acc[e], o);
    }
    if (lane == 0) {
        int i1 = 0; float v1 = acc[0];
#pragma unroll
        for (int e = 1; e < N_EXP; e++) if (acc[e] > v1) { v1 = acc[e]; i1 = e; }
        int i2 = -1; float v2 = -INFINITY;
#pragma unroll
        for (int e = 0; e < N_EXP; e++) if (e != i1 && acc[e] > v2) { v2 = acc[e]; i2 = e; }
        float e2 = expf(v2 - v1);
        float inv = 1.0f / (1.0f + e2);
        int s1 = atomicAdd(&g_count[i1], 1);
        g_tok[i1 * MAXPE + s1] = warp;  g_wt[i1 * MAXPE + s1] = inv;
        int s2 = atomicAdd(&g_count[i2], 1);
        g_tok[i2 * MAXPE + s2] = warp;  g_wt[i2 * MAXPE + s2] = e2 * inv;
    }
}

__global__ void offsets_kernel() {
    int s = 0;
    for (int e = 0; e < N_EXP; e++) { g_offset[e] = s; s += g_count[e]; }
    g_offset[N_EXP] = s;
}

// ---------------------------------------------------------------------------
// Grouped GEMM, fp16 2-term. Tile M=128 x N=128, K-chunk 64, 8 warps (4Mx2N),
// warp tile 32x64. smem/stage: Ahi 16K | Alo 16K | B 16K = 48K, 2 stages.
// Swizzle: 16B chunk c of 128B row r at (c ^ (r&7)).
// ---------------------------------------------------------------------------
#define AHI_OFF 0
#define ALO_OFF 16384
#define B_OFF   32768
#define STG     49152
#define SMEM_BYTES (2 * STG)

template <int PHASE>
__global__ __launch_bounds__(256, 1)
void ffn_hmma_kernel(const float* __restrict__ Abase,
                     const float* __restrict__ W,
                     const float* __restrict__ bias,
                     float* __restrict__ out)
{
    constexpr int KTOT = (PHASE == 1) ? D_MODEL : D_FF;
    constexpr int NTOT = (PHASE == 1) ? D_FF : D_MODEL;
    constexpr int LDA  = (PHASE == 1) ? D_MODEL : D_FF;
    constexpr int L    = KTOT / 64;

    const int e   = blockIdx.z;
    const int cnt = g_count[e];
    const int m0  = blockIdx.y * 128;
    if (m0 >= cnt) return;
    const int n0    = blockIdx.x * 128;
    const int e_off = g_offset[e];
    const float* We = W + (size_t)e * KTOT * NTOT;

    extern __shared__ char smem[];
    const uint32_t smem_u = smem_to_u32(smem);
    const int tid  = threadIdx.x;
    const int wid  = tid >> 5;
    const int lane = tid & 31;
    const int wm   = wid >> 1;
    const int wn   = wid & 1;

    // ---- gmem source pointers for staging (identical to R5) ----
    const float* arow[8];
#pragma unroll
    for (int it = 0; it < 8; it++) {
        int m = it * 16 + (tid >> 4);
        int slot = m0 + m; if (slot >= cnt) slot = cnt - 1;
        int r = (PHASE == 1) ? g_tok[e * MAXPE + slot] : (e_off + slot);
        const float* base = (PHASE == 1) ? Abase : (const float*)g_H;
        arow[it] = base + (size_t)r * LDA;
    }
    const int nB = tid & 127;
    const int kh = tid >> 7;
    const float* Wcol = We + n0 + nB;

    // ---- ldmatrix lane addressing (validated in R5) ----
    const int a_row0 = wm * 32 + (lane & 7) + (lane & 8);
    const int a_kt   = (lane >> 4) & 1;
    const int b_row0 = wn * 64 + (lane & 7) + ((lane & 16) ? 8 : 0);
    const int b_kt   = (lane >> 3) & 1;

    float acc[2][8][4];
#pragma unroll
    for (int mb = 0; mb < 2; mb++)
#pragma unroll
        for (int nb = 0; nb < 8; nb++)
#pragma unroll
            for (int q = 0; q < 4; q++) acc[mb][nb][q] = 0.0f;

    float4 aR[8];
    float  bR[32];

    auto ldg_chunk = [&](int c) {
        const int k0 = c * 64;
#pragma unroll
        for (int it = 0; it < 8; it++)
            aR[it] = *reinterpret_cast<const float4*>(arow[it] + k0 + (tid & 15) * 4);
#pragma unroll
        for (int kb = 0; kb < 4; kb++)
#pragma unroll
            for (int j = 0; j < 8; j++)
                bR[kb * 8 + j] = __ldg(Wcol + (size_t)(k0 + kh * 32 + kb * 8 + j) * NTOT);
    };
    auto sts_chunk = [&](int buf) {
        char* stage = smem + buf * STG;
#pragma unroll
        for (int it = 0; it < 8; it++) {
            int m  = it * 16 + (tid >> 4);
            int cA = (tid & 15) * 8;
            int off = m * 128 + (cA ^ ((m & 7) << 4));
            uint32_t h0, l0, h1, l1;
            split2(aR[it].x, aR[it].y, h0, l0);
            split2(aR[it].z, aR[it].w, h1, l1);
            *reinterpret_cast<uint2*>(stage + AHI_OFF + off) = make_uint2(h0, h1);
            *reinterpret_cast<uint2*>(stage + ALO_OFF + off) = make_uint2(l0, l1);
        }
#pragma unroll
        for (int kb = 0; kb < 4; kb++) {
            int cB = kh * 64 + kb * 16;
            int off = nB * 128 + (cB ^ ((nB & 7) << 4));
            uint32_t w[4];
#pragma unroll
            for (int p = 0; p < 4; p++)
                w[p] = packf16(bR[kb * 8 + p * 2], bR[kb * 8 + p * 2 + 1]);
            *reinterpret_cast<uint4*>(stage + B_OFF + off) = make_uint4(w[0], w[1], w[2], w[3]);
        }
    };

    // ---- prologue: chunk 0 staged; chunk 1 LDGs in flight ----
    ldg_chunk(0);
    sts_chunk(0);
    __syncthreads();
    if (L > 1) ldg_chunk(1);

    for (int c = 0; c < L; c++) {
        const uint32_t stage_u = smem_u + (c & 1) * STG;
        // ---- compute chunk c (LDGs for chunk c+1 already in flight) ----
#pragma unroll
        for (int ks = 0; ks < 4; ks++) {
            uint32_t ah[2][4], al[2][4], bb[4][4];
#pragma unroll
            for (int mb = 0; mb < 2; mb++) {
                int row = a_row0 + mb * 16;
                uint32_t off = row * 128 + (((2 * ks + a_kt) ^ (row & 7)) << 4);
                LDSM_X4(ah[mb], stage_u + AHI_OFF + off);
                LDSM_X4(al[mb], stage_u + ALO_OFF + off);
            }
#pragma unroll
            for (int np = 0; np < 4; np++) {
                int row = b_row0 + np * 16;
                uint32_t off = row * 128 + (((2 * ks + b_kt) ^ (row & 7)) << 4);
                LDSM_X4(bb[np], stage_u + B_OFF + off);
            }
#pragma unroll
            for (int mb = 0; mb < 2; mb++)
#pragma unroll
                for (int nb = 0; nb < 8; nb++)
                    mma_f16(acc[mb][nb], ah[mb], &bb[nb >> 1][(nb & 1) * 2]);
#pragma unroll
            for (int mb = 0; mb < 2; mb++)
#pragma unroll
                for (int nb = 0; nb < 8; nb++)
                    mma_f16(acc[mb][nb], al[mb], &bb[nb >> 1][(nb & 1) * 2]);
        }
        // ---- rotate: store chunk c+1, start LDGs for chunk c+2 ----
        if (c + 1 < L) {
            __syncthreads();                 // everyone done reading stage (c+1)&1
            sts_chunk((c + 1) & 1);
            if (c + 2 < L) ldg_chunk(c + 2); // latency hides under next compute
            __syncthreads();                 // staging visible
        }
    }

    // ---- epilogue (identical to R5) ----
    const int gp = lane >> 2;
    const int qq = lane & 3;
#pragma unroll
    for (int mb = 0; mb < 2; mb++) {
#pragma unroll
        for (int h = 0; h < 2; h++) {
            int mloc = wm * 32 + mb * 16 + gp + h * 8;
            int slot = m0 + mloc;
            if (slot >= cnt) continue;
            if (PHASE == 1) {
                float* hrow = g_H + (size_t)(e_off + slot) * D_FF;
#pragma unroll
                for (int nb = 0; nb < 8; nb++) {
                    int cidx = n0 + wn * 64 + nb * 8 + qq * 2;
                    float v0 = acc[mb][nb][h * 2 + 0] + __ldg(bias + e * NTOT + cidx + 0);
                    float v1 = acc[mb][nb][h * 2 + 1] + __ldg(bias + e * NTOT + cidx + 1);
                    float2 o;
                    o.x = v0 / (1.0f + __expf(-v0));
                    o.y = v1 / (1.0f + __expf(-v1));
                    *reinterpret_cast<float2*>(hrow + cidx) = o;
                }
            } else {
                int   tok = g_tok[e * MAXPE + slot];
                float w   = g_wt[e * MAXPE + slot];
                float* orow = out + (size_t)tok * D_MODEL;
#pragma unroll
                for (int nb = 0; nb < 8; nb++) {
                    int cidx = n0 + wn * 64 + nb * 8 + qq * 2;
                    float v0 = acc[mb][nb][h * 2 + 0] + __ldg(bias + e * NTOT + cidx + 0);
                    float v1 = acc[mb][nb][h * 2 + 1] + __ldg(bias + e * NTOT + cidx + 1);
                    atomicAdd(orow + cidx + 0, w * v0);
                    atomicAdd(orow + cidx + 1, w * v1);
                }
            }
        }
    }
}

// ---------------------------------------------------------------------------
extern "C" void kernel_launch(void* const* d_in, const int* in_sizes, int n_in,
                              void* d_out, int out_size) {
    const float* x  = (const float*)d_in[0];  // [2,2048,1024]
    const float* W1 = (const float*)d_in[1];  // [16,1024,4096]
    const float* b1 = (const float*)d_in[2];  // [16,4096]
    const float* W2 = (const float*)d_in[3];  // [16,4096,1024]
    const float* b2 = (const float*)d_in[4];  // [16,1024]
    const float* Wg = (const float*)d_in[5];  // [1024,16]
    float* out = (float*)d_out;               // [2,2048,1024]

    cudaFuncSetAttribute(ffn_hmma_kernel<1>, cudaFuncAttributeMaxDynamicSharedMemorySize, SMEM_BYTES);
    cudaFuncSetAttribute(ffn_hmma_kernel<2>, cudaFuncAttributeMaxDynamicSharedMemorySize, SMEM_BYTES);

    reset_kernel<<<4096, 256>>>(out, out_size);
    gating_kernel<<<N_TOK / 8, 256>>>(x, Wg);
    offsets_kernel<<<1, 1>>>();
    ffn_hmma_kernel<1><<<dim3(D_FF / 128, MAXPE / 128, N_EXP), 256, SMEM_BYTES>>>(x, W1, b1, out);
    ffn_hmma_kernel<2><<<dim3(D_MODEL / 128, MAXPE / 128, N_EXP), 256, SMEM_BYTES>>>(nullptr, W2, b2, out);
}

// round 9
// speedup vs baseline: 3.6100x; 1.0299x over previous
#include <cuda_runtime.h>
#include <cuda_fp16.h>
#include <cstdint>
#include <math.h>

// MoE top-2/16, fp32 in/out.
// gate -> bucket -> pre-convert (x gather fp16 hi/lo; W1/W2 transpose fp16 [e][n][k])
// -> grouped HMMA fp16 GEMM1 (A 2-term split, +swish, H stored fp16 hi/lo)
// -> grouped HMMA fp16 GEMM2 -> weighted atomic scatter.
// Mainloop: pure cp.async 4-stage ring + ldmatrix + mma.sync.m16n8k16.
// NOTE: all __device__ scratch is referenced ONLY from device code (R6 bug: host-passed symbols).

#define D_MODEL 1024
#define N_EXP   16
#define D_FF    4096
#define N_TOK   4096
#define MAXPE   4096
#define NSLOT   (2 * N_TOK)

__device__ int    g_count[N_EXP];
__device__ int    g_offset[N_EXP + 1];
__device__ int    g_tok[N_EXP * MAXPE];
__device__ float  g_wt[N_EXP * MAXPE];
__device__ __half g_W1t[(size_t)N_EXP * D_FF * D_MODEL];   // [e][n][k]
__device__ __half g_W2t[(size_t)N_EXP * D_MODEL * D_FF];   // [e][n][k]
__device__ __half g_Ah[(size_t)NSLOT * D_MODEL];
__device__ __half g_Al[(size_t)NSLOT * D_MODEL];
__device__ __half g_Hh[(size_t)NSLOT * D_FF];
__device__ __half g_Hl[(size_t)NSLOT * D_FF];

// ---------------------------------------------------------------------------
__device__ __forceinline__ uint32_t smem_to_u32(const void* p) {
    uint32_t a;
    asm("{ .reg .u64 t; cvta.to.shared.u64 t, %1; cvt.u32.u64 %0, t; }" : "=r"(a) : "l"(p));
    return a;
}
__device__ __forceinline__ void cp16(uint32_t dst, const void* src) {
    asm volatile("cp.async.cg.shared.global [%0], [%1], 16;" :: "r"(dst), "l"(src));
}
#define CP_COMMIT() asm volatile("cp.async.commit_group;" ::: "memory")
#define CP_WAIT2()  asm volatile("cp.async.wait_group 2;" ::: "memory")

#define LDSM_X4(r, a)                                                            \
    asm volatile("ldmatrix.sync.aligned.m8n8.x4.shared.b16 {%0,%1,%2,%3}, [%4];" \
        : "=r"((r)[0]), "=r"((r)[1]), "=r"((r)[2]), "=r"((r)[3]) : "r"(a))

__device__ __forceinline__ void mma_f16(float* d, const uint32_t* a, const uint32_t* b) {
    asm volatile("mma.sync.aligned.m16n8k16.row.col.f32.f16.f16.f32 "
        "{%0,%1,%2,%3}, {%4,%5,%6,%7}, {%8,%9}, {%0,%1,%2,%3};"
        : "+f"(d[0]), "+f"(d[1]), "+f"(d[2]), "+f"(d[3])
        : "r"(a[0]), "r"(a[1]), "r"(a[2]), "r"(a[3]), "r"(b[0]), "r"(b[1]));
}

// pack(a, b): a -> low half, b -> high half (memory order [a, b])
__device__ __forceinline__ uint32_t packf16(float a, float b) {
    uint32_t r;
    asm("cvt.rn.f16x2.f32 %0, %1, %2;" : "=r"(r) : "f"(b), "f"(a));
    return r;
}
__device__ __forceinline__ void split2(float a, float b, uint32_t& hi, uint32_t& lo) {
    uint32_t h = packf16(a, b);
    __half2 hh = *reinterpret_cast<__half2*>(&h);
    float ah = __low2float(hh), bh = __high2float(hh);
    hi = h;
    lo = packf16(a - ah, b - bh);
}

// ---------------------------------------------------------------------------
// reset / gating / offsets (validated in R5/R8)
// ---------------------------------------------------------------------------
__global__ void reset_kernel(float* __restrict__ out, int out_size) {
    int i = blockIdx.x * blockDim.x + threadIdx.x;
    if (i < N_EXP) g_count[i] = 0;
    for (int j = i; j < out_size; j += gridDim.x * blockDim.x) out[j] = 0.0f;
}

__global__ void gating_kernel(const float* __restrict__ x, const float* __restrict__ Wg) {
    int warp = (blockIdx.x * blockDim.x + threadIdx.x) >> 5;
    int lane = threadIdx.x & 31;
    if (warp >= N_TOK) return;
    const float* xr = x + (size_t)warp * D_MODEL;
    float acc[N_EXP];
#pragma unroll
    for (int e = 0; e < N_EXP; e++) acc[e] = 0.0f;
    for (int d = lane; d < D_MODEL; d += 32) {
        float xv = xr[d];
        const float* wr = Wg + d * N_EXP;
#pragma unroll
        for (int e = 0; e < N_EXP; e++) acc[e] = fmaf(xv, wr[e], acc[e]);
    }
#pragma unroll
    for (int e = 0; e < N_EXP; e++) {
#pragma unroll
        for (int o = 16; o > 0; o >>= 1) acc[e] += __shfl_xor_sync(0xffffffffu, acc[e], o);
    }
    if (lane == 0) {
        int i1 = 0; float v1 = acc[0];
#pragma unroll
        for (int e = 1; e < N_EXP; e++) if (acc[e] > v1) { v1 = acc[e]; i1 = e; }
        int i2 = -1; float v2 = -INFINITY;
#pragma unroll
        for (int e = 0; e < N_EXP; e++) if (e != i1 && acc[e] > v2) { v2 = acc[e]; i2 = e; }
        float e2 = expf(v2 - v1);
        float inv = 1.0f / (1.0f + e2);
        int s1 = atomicAdd(&g_count[i1], 1);
        g_tok[i1 * MAXPE + s1] = warp;  g_wt[i1 * MAXPE + s1] = inv;
        int s2 = atomicAdd(&g_count[i2], 1);
        g_tok[i2 * MAXPE + s2] = warp;  g_wt[i2 * MAXPE + s2] = e2 * inv;
    }
}

__global__ void offsets_kernel() {
    int s = 0;
    for (int e = 0; e < N_EXP; e++) { g_offset[e] = s; s += g_count[e]; }
    g_offset[N_EXP] = s;
}

// ---------------------------------------------------------------------------
// Pre-pass: gather x rows in expert-slot order, split to fp16 hi/lo.
// ---------------------------------------------------------------------------
__global__ void gatherx_kernel(const float* __restrict__ x) {
    int s = blockIdx.x;
    if (s >= g_offset[N_EXP]) return;
    int e = 0;
#pragma unroll
    for (int i = 0; i < N_EXP - 1; i++) if (s >= g_offset[i + 1]) e = i + 1;
    int tok = g_tok[e * MAXPE + (s - g_offset[e])];
    const float* xr = x + (size_t)tok * D_MODEL;
    int c = threadIdx.x * 8;
    float4 a = *reinterpret_cast<const float4*>(xr + c);
    float4 b = *reinterpret_cast<const float4*>(xr + c + 4);
    float v[8] = {a.x, a.y, a.z, a.w, b.x, b.y, b.z, b.w};
    uint32_t hi[4], lo[4];
#pragma unroll
    for (int q = 0; q < 4; q++) split2(v[2 * q], v[2 * q + 1], hi[q], lo[q]);
    *reinterpret_cast<uint4*>(g_Ah + (size_t)s * D_MODEL + c) = make_uint4(hi[0], hi[1], hi[2], hi[3]);
    *reinterpret_cast<uint4*>(g_Al + (size_t)s * D_MODEL + c) = make_uint4(lo[0], lo[1], lo[2], lo[3]);
}

// ---------------------------------------------------------------------------
// Pre-pass: convert+transpose weights. src [e][K][N] fp32 -> g_W{1,2}t [e][N][K] fp16.
// Destination selected by template ON DEVICE (never pass device symbols from host).
// ---------------------------------------------------------------------------
template <int WHICH>
__global__ void convW_kernel(const float* __restrict__ src) {
    constexpr int K = (WHICH == 1) ? D_MODEL : D_FF;
    constexpr int N = (WHICH == 1) ? D_FF : D_MODEL;
    __half* dstBase = (WHICH == 1) ? g_W1t : g_W2t;
    __shared__ float t[64][65];
    int e  = blockIdx.z;
    int k0 = blockIdx.y * 64;
    int n0 = blockIdx.x * 64;
    const float* S = src + (size_t)e * K * N;
    int tid = threadIdx.x;
    int rk = tid >> 4;
    int cn = (tid & 15) * 4;
#pragma unroll
    for (int p = 0; p < 4; p++) {
        float4 v = *reinterpret_cast<const float4*>(S + (size_t)(k0 + p * 16 + rk) * N + n0 + cn);
        t[p * 16 + rk][cn + 0] = v.x;
        t[p * 16 + rk][cn + 1] = v.y;
        t[p * 16 + rk][cn + 2] = v.z;
        t[p * 16 + rk][cn + 3] = v.w;
    }
    __syncthreads();
    int n  = tid >> 2;
    int kq = (tid & 3) * 16;
    uint32_t w[8];
#pragma unroll
    for (int q = 0; q < 8; q++)
        w[q] = packf16(t[kq + 2 * q][n], t[kq + 2 * q + 1][n]);
    __half* D = dstBase + (size_t)e * N * K + (size_t)(n0 + n) * K + k0 + kq;
    *reinterpret_cast<uint4*>(D)     = make_uint4(w[0], w[1], w[2], w[3]);
    *reinterpret_cast<uint4*>(D + 8) = make_uint4(w[4], w[5], w[6], w[7]);
}

// ---------------------------------------------------------------------------
// Grouped GEMM, fp16 2-term (A hi/lo, B single). Tile M=128 x N=128, K-chunk 64,
// 8 warps (4Mx2N), warp tile 32x64. Stage: Ahi 16K | Alo 16K | B 16K = 48K;
// 4 stages, cp.async prefetch depth 3. Swizzle: chunk c of row r at (c ^ (r&7)).
// ---------------------------------------------------------------------------
#define AHI_OFF 0
#define ALO_OFF 16384
#define B_OFF   32768
#define STG     49152
#define SMEM_BYTES (4 * STG)

template <int PHASE>
__global__ __launch_bounds__(256, 1)
void ffn_kernel(const float* __restrict__ bias, float* __restrict__ out)
{
    constexpr int KTOT = (PHASE == 1) ? D_MODEL : D_FF;
    constexpr int NTOT = (PHASE == 1) ? D_FF : D_MODEL;
    constexpr int L    = KTOT / 64;

    const int e   = blockIdx.z;
    const int cnt = g_count[e];
    const int m0  = blockIdx.y * 128;
    if (m0 >= cnt) return;
    const int n0    = blockIdx.x * 128;
    const int e_off = g_offset[e];

    // device-side scratch selection (device addresses, not host shadows)
    const __half* Ah = (PHASE == 1) ? g_Ah : g_Hh;
    const __half* Al = (PHASE == 1) ? g_Al : g_Hl;
    const __half* Be = ((PHASE == 1) ? g_W1t : g_W2t) + (size_t)e * NTOT * KTOT;

    extern __shared__ char smem[];
    const uint32_t smem_u = smem_to_u32(smem);
    const int tid  = threadIdx.x;
    const int lane = tid & 31;
    const int wid  = tid >> 5;
    const int wm   = wid >> 1;
    const int wn   = wid & 1;

    // cp.async src/dst: 4 (row, 16B-chunk) pairs per thread covering 128x128B
    const __half* sAh[4]; const __half* sAl[4]; const __half* sB[4];
    uint32_t dOff[4];
#pragma unroll
    for (int i = 0; i < 4; i++) {
        int id  = tid + 256 * i;
        int row = id >> 3;
        int c   = id & 7;
        int slot = m0 + row; if (slot >= cnt) slot = cnt - 1;
        size_t aidx = (size_t)(e_off + slot) * KTOT + c * 8;
        sAh[i]  = Ah + aidx;
        sAl[i]  = Al + aidx;
        sB[i]   = Be + (size_t)(n0 + row) * KTOT + c * 8;
        dOff[i] = row * 128 + ((c ^ (row & 7)) << 4);
    }

    // ldmatrix lane addressing (validated R5/R8)
    const int a_row0 = wm * 32 + (lane & 7) + (lane & 8);
    const int a_kt   = (lane >> 4) & 1;
    const int b_row0 = wn * 64 + (lane & 7) + ((lane & 16) ? 8 : 0);
    const int b_kt   = (lane >> 3) & 1;

    float acc[2][8][4];
#pragma unroll
    for (int mb = 0; mb < 2; mb++)
#pragma unroll
        for (int nb = 0; nb < 8; nb++)
#pragma unroll
            for (int q = 0; q < 4; q++) acc[mb][nb][q] = 0.0f;

    // prologue: prefetch stages 0..2
#pragma unroll
    for (int p = 0; p < 3; p++) {
        if (p < L) {
            uint32_t st = smem_u + p * STG;
            int k0 = p * 64;
#pragma unroll
            for (int i = 0; i < 4; i++) {
                cp16(st + AHI_OFF + dOff[i], sAh[i] + k0);
                cp16(st + ALO_OFF + dOff[i], sAl[i] + k0);
                cp16(st + B_OFF   + dOff[i], sB[i]  + k0);
            }
        }
        CP_COMMIT();
    }

    for (int c = 0; c < L; c++) {
        CP_WAIT2();
        __syncthreads();
        if (c + 3 < L) {
            uint32_t st = smem_u + ((c + 3) & 3) * STG;
            int k0 = (c + 3) * 64;
#pragma unroll
            for (int i = 0; i < 4; i++) {
                cp16(st + AHI_OFF + dOff[i], sAh[i] + k0);
                cp16(st + ALO_OFF + dOff[i], sAl[i] + k0);
                cp16(st + B_OFF   + dOff[i], sB[i]  + k0);
            }
        }
        CP_COMMIT();

        const uint32_t st = smem_u + (c & 3) * STG;
#pragma unroll
        for (int ks = 0; ks < 4; ks++) {
            uint32_t ah[2][4], al[2][4], bb[4][4];
#pragma unroll
            for (int mb = 0; mb < 2; mb++) {
                int row = a_row0 + mb * 16;
                uint32_t off = row * 128 + (((2 * ks + a_kt) ^ (row & 7)) << 4);
                LDSM_X4(ah[mb], st + AHI_OFF + off);
                LDSM_X4(al[mb], st + ALO_OFF + off);
            }
#pragma unroll
            for (int np = 0; np < 4; np++) {
                int row = b_row0 + np * 16;
                uint32_t off = row * 128 + (((2 * ks + b_kt) ^ (row & 7)) << 4);
                LDSM_X4(bb[np], st + B_OFF + off);
            }
#pragma unroll
            for (int mb = 0; mb < 2; mb++)
#pragma unroll
                for (int nb = 0; nb < 8; nb++)
                    mma_f16(acc[mb][nb], ah[mb], &bb[nb >> 1][(nb & 1) * 2]);
#pragma unroll
            for (int mb = 0; mb < 2; mb++)
#pragma unroll
                for (int nb = 0; nb < 8; nb++)
                    mma_f16(acc[mb][nb], al[mb], &bb[nb >> 1][(nb & 1) * 2]);
        }
    }

    // epilogue
    const int gp = lane >> 2;
    const int qq = lane & 3;
#pragma unroll
    for (int mb = 0; mb < 2; mb++) {
#pragma unroll
        for (int h = 0; h < 2; h++) {
            int mloc = wm * 32 + mb * 16 + gp + h * 8;
            int slot = m0 + mloc;
            if (slot >= cnt) continue;
            if (PHASE == 1) {
                size_t hrow = (size_t)(e_off + slot) * D_FF;
#pragma unroll
                for (int nb = 0; nb < 8; nb++) {
                    int cidx = n0 + wn * 64 + nb * 8 + qq * 2;
                    float v0 = acc[mb][nb][h * 2 + 0] + __ldg(bias + e * NTOT + cidx + 0);
                    float v1 = acc[mb][nb][h * 2 + 1] + __ldg(bias + e * NTOT + cidx + 1);
                    float s0 = v0 / (1.0f + __expf(-v0));
                    float s1 = v1 / (1.0f + __expf(-v1));
                    uint32_t hi, lo;
                    split2(s0, s1, hi, lo);
                    *reinterpret_cast<uint32_t*>(g_Hh + hrow + cidx) = hi;
                    *reinterpret_cast<uint32_t*>(g_Hl + hrow + cidx) = lo;
                }
            } else {
                int   tok = g_tok[e * MAXPE + slot];
                float w   = g_wt[e * MAXPE + slot];
                float* orow = out + (size_t)tok * D_MODEL;
#pragma unroll
                for (int nb = 0; nb < 8; nb++) {
                    int cidx = n0 + wn * 64 + nb * 8 + qq * 2;
                    float v0 = acc[mb][nb][h * 2 + 0] + __ldg(bias + e * NTOT + cidx + 0);
                    float v1 = acc[mb][nb][h * 2 + 1] + __ldg(bias + e * NTOT + cidx + 1);
                    atomicAdd(orow + cidx + 0, w * v0);
                    atomicAdd(orow + cidx + 1, w * v1);
                }
            }
        }
    }
}

// ---------------------------------------------------------------------------
extern "C" void kernel_launch(void* const* d_in, const int* in_sizes, int n_in,
                              void* d_out, int out_size) {
    const float* x  = (const float*)d_in[0];
    const float* W1 = (const float*)d_in[1];
    const float* b1 = (const float*)d_in[2];
    const float* W2 = (const float*)d_in[3];
    const float* b2 = (const float*)d_in[4];
    const float* Wg = (const float*)d_in[5];
    float* out = (float*)d_out;

    cudaFuncSetAttribute(ffn_kernel<1>, cudaFuncAttributeMaxDynamicSharedMemorySize, SMEM_BYTES);
    cudaFuncSetAttribute(ffn_kernel<2>, cudaFuncAttributeMaxDynamicSharedMemorySize, SMEM_BYTES);

    reset_kernel<<<4096, 256>>>(out, out_size);
    gating_kernel<<<N_TOK / 8, 256>>>(x, Wg);
    offsets_kernel<<<1, 1>>>();
    gatherx_kernel<<<NSLOT, 128>>>(x);
    convW_kernel<1><<<dim3(D_FF / 64, D_MODEL / 64, N_EXP), 256>>>(W1);
    convW_kernel<2><<<dim3(D_MODEL / 64, D_FF / 64, N_EXP), 256>>>(W2);
    ffn_kernel<1><<<dim3(D_FF / 128, MAXPE / 128, N_EXP), 256, SMEM_BYTES>>>(b1, out);
    ffn_kernel<2><<<dim3(D_MODEL / 128, MAXPE / 128, N_EXP), 256, SMEM_BYTES>>>(b2, out);
}

// round 11
// speedup vs baseline: 6.0605x; 1.6788x over previous
#include <cuda_runtime.h>
#include <cuda_fp16.h>
#include <cstdint>
#include <math.h>

// MoE top-2/16, fp32 in/out.
// gate -> bucket -> pre-convert (x gather fp16; W1/W2 transpose fp16 [e][n][k])
// -> grouped HMMA fp16 GEMM1 (+swish, H fp16) -> grouped GEMM2 -> weighted scatter.
// Mainloop: pure cp.async 3-stage ring + ldmatrix + mma.sync.m16n8k16, 2 CTAs/SM.

#define D_MODEL 1024
#define N_EXP   16
#define D_FF    4096
#define N_TOK   4096
#define MAXPE   4096
#define NSLOT   (2 * N_TOK)

__device__ int    g_count[N_EXP];
__device__ int    g_offset[N_EXP + 1];
__device__ int    g_tok[N_EXP * MAXPE];
__device__ float  g_wt[N_EXP * MAXPE];
__device__ __half g_W1t[(size_t)N_EXP * D_FF * D_MODEL];   // [e][n][k]
__device__ __half g_W2t[(size_t)N_EXP * D_MODEL * D_FF];   // [e][n][k]
__device__ __half g_A[(size_t)NSLOT * D_MODEL];            // gathered x fp16
__device__ __half g_Hf[(size_t)NSLOT * D_FF];              // H fp16

// ---------------------------------------------------------------------------
__device__ __forceinline__ uint32_t smem_to_u32(const void* p) {
    uint32_t a;
    asm("{ .reg .u64 t; cvta.to.shared.u64 t, %1; cvt.u32.u64 %0, t; }" : "=r"(a) : "l"(p));
    return a;
}
__device__ __forceinline__ void cp16(uint32_t dst, const void* src) {
    asm volatile("cp.async.cg.shared.global [%0], [%1], 16;" :: "r"(dst), "l"(src));
}
#define CP_COMMIT() asm volatile("cp.async.commit_group;" ::: "memory")
#define CP_WAIT1()  asm volatile("cp.async.wait_group 1;" ::: "memory")

#define LDSM_X4(r, a)                                                            \
    asm volatile("ldmatrix.sync.aligned.m8n8.x4.shared.b16 {%0,%1,%2,%3}, [%4];" \
        : "=r"((r)[0]), "=r"((r)[1]), "=r"((r)[2]), "=r"((r)[3]) : "r"(a))

__device__ __forceinline__ void mma_f16(float* d, const uint32_t* a, const uint32_t* b) {
    asm volatile("mma.sync.aligned.m16n8k16.row.col.f32.f16.f16.f32 "
        "{%0,%1,%2,%3}, {%4,%5,%6,%7}, {%8,%9}, {%0,%1,%2,%3};"
        : "+f"(d[0]), "+f"(d[1]), "+f"(d[2]), "+f"(d[3])
        : "r"(a[0]), "r"(a[1]), "r"(a[2]), "r"(a[3]), "r"(b[0]), "r"(b[1]));
}

// pack(a, b): a -> low half, b -> high half (memory order [a, b])
__device__ __forceinline__ uint32_t packf16(float a, float b) {
    uint32_t r;
    asm("cvt.rn.f16x2.f32 %0, %1, %2;" : "=r"(r) : "f"(b), "f"(a));
    return r;
}

// ---------------------------------------------------------------------------
// reset / gating / offsets (validated R5/R8/R9)
// ---------------------------------------------------------------------------
__global__ void reset_kernel(float* __restrict__ out, int out_size) {
    int i = blockIdx.x * blockDim.x + threadIdx.x;
    if (i < N_EXP) g_count[i] = 0;
    for (int j = i; j < out_size; j += gridDim.x * blockDim.x) out[j] = 0.0f;
}

__global__ void gating_kernel(const float* __restrict__ x, const float* __restrict__ Wg) {
    int warp = (blockIdx.x * blockDim.x + threadIdx.x) >> 5;
    int lane = threadIdx.x & 31;
    if (warp >= N_TOK) return;
    const float* xr = x + (size_t)warp * D_MODEL;
    float acc[N_EXP];
#pragma unroll
    for (int e = 0; e < N_EXP; e++) acc[e] = 0.0f;
    for (int d = lane; d < D_MODEL; d += 32) {
        float xv = xr[d];
        const float* wr = Wg + d * N_EXP;
#pragma unroll
        for (int e = 0; e < N_EXP; e++) acc[e] = fmaf(xv, wr[e], acc[e]);
    }
#pragma unroll
    for (int e = 0; e < N_EXP; e++) {
#pragma unroll
        for (int o = 16; o > 0; o >>= 1) acc[e] += __shfl_xor_sync(0xffffffffu, acc[e], o);
    }
    if (lane == 0) {
        int i1 = 0; float v1 = acc[0];
#pragma unroll
        for (int e = 1; e < N_EXP; e++) if (acc[e] > v1) { v1 = acc[e]; i1 = e; }
        int i2 = -1; float v2 = -INFINITY;
#pragma unroll
        for (int e = 0; e < N_EXP; e++) if (e != i1 && acc[e] > v2) { v2 = acc[e]; i2 = e; }
        float e2 = expf(v2 - v1);
        float inv = 1.0f / (1.0f + e2);
        int s1 = atomicAdd(&g_count[i1], 1);
        g_tok[i1 * MAXPE + s1] = warp;  g_wt[i1 * MAXPE + s1] = inv;
        int s2 = atomicAdd(&g_count[i2], 1);
        g_tok[i2 * MAXPE + s2] = warp;  g_wt[i2 * MAXPE + s2] = e2 * inv;
    }
}

__global__ void offsets_kernel() {
    int s = 0;
    for (int e = 0; e < N_EXP; e++) { g_offset[e] = s; s += g_count[e]; }
    g_offset[N_EXP] = s;
}

// ---------------------------------------------------------------------------
// Pre-pass: gather x rows in expert-slot order -> fp16.
// ---------------------------------------------------------------------------
__global__ void gatherx_kernel(const float* __restrict__ x) {
    int s = blockIdx.x;
    if (s >= g_offset[N_EXP]) return;
    int e = 0;
#pragma unroll
    for (int i = 0; i < N_EXP - 1; i++) if (s >= g_offset[i + 1]) e = i + 1;
    int tok = g_tok[e * MAXPE + (s - g_offset[e])];
    const float* xr = x + (size_t)tok * D_MODEL;
    int c = threadIdx.x * 8;
    float4 a = *reinterpret_cast<const float4*>(xr + c);
    float4 b = *reinterpret_cast<const float4*>(xr + c + 4);
    uint4 o;
    o.x = packf16(a.x, a.y);
    o.y = packf16(a.z, a.w);
    o.z = packf16(b.x, b.y);
    o.w = packf16(b.z, b.w);
    *reinterpret_cast<uint4*>(g_A + (size_t)s * D_MODEL + c) = o;
}

// ---------------------------------------------------------------------------
// Pre-pass: convert+transpose weights. src [e][K][N] fp32 -> [e][N][K] fp16.
// Destination selected by template ON DEVICE.
// ---------------------------------------------------------------------------
template <int WHICH>
__global__ void convW_kernel(const float* __restrict__ src) {
    constexpr int K = (WHICH == 1) ? D_MODEL : D_FF;
    constexpr int N = (WHICH == 1) ? D_FF : D_MODEL;
    __half* dstBase = (WHICH == 1) ? g_W1t : g_W2t;
    __shared__ float t[64][65];
    int e  = blockIdx.z;
    int k0 = blockIdx.y * 64;
    int n0 = blockIdx.x * 64;
    const float* S = src + (size_t)e * K * N;
    int tid = threadIdx.x;
    int rk = tid >> 4;
    int cn = (tid & 15) * 4;
#pragma unroll
    for (int p = 0; p < 4; p++) {
        float4 v = *reinterpret_cast<const float4*>(S + (size_t)(k0 + p * 16 + rk) * N + n0 + cn);
        t[p * 16 + rk][cn + 0] = v.x;
        t[p * 16 + rk][cn + 1] = v.y;
        t[p * 16 + rk][cn + 2] = v.z;
        t[p * 16 + rk][cn + 3] = v.w;
    }
    __syncthreads();
    int n  = tid >> 2;
    int kq = (tid & 3) * 16;
    uint32_t w[8];
#pragma unroll
    for (int q = 0; q < 8; q++)
        w[q] = packf16(t[kq + 2 * q][n], t[kq + 2 * q + 1][n]);
    __half* D = dstBase + (size_t)e * N * K + (size_t)(n0 + n) * K + k0 + kq;
    *reinterpret_cast<uint4*>(D)     = make_uint4(w[0], w[1], w[2], w[3]);
    *reinterpret_cast<uint4*>(D + 8) = make_uint4(w[4], w[5], w[6], w[7]);
}

// ---------------------------------------------------------------------------
// Grouped GEMM, single fp16. Tile M=128 x N=128, K-chunk 64, 8 warps (4Mx2N),
// warp tile 32x64. Stage: A 16K | B 16K = 32K; 3 stages (96K) -> 2 CTAs/SM.
// cp.async depth 2, wait_group 1. Swizzle: 16B chunk c of row r at (c ^ (r&7)).
// ---------------------------------------------------------------------------
#define A_OFF 0
#define B_OFF 16384
#define STG   32768
#define SMEM_BYTES (3 * STG)

template <int PHASE>
__global__ __launch_bounds__(256, 2)
void ffn_kernel(const float* __restrict__ bias, float* __restrict__ out)
{
    constexpr int KTOT = (PHASE == 1) ? D_MODEL : D_FF;
    constexpr int NTOT = (PHASE == 1) ? D_FF : D_MODEL;
    constexpr int L    = KTOT / 64;

    const int e   = blockIdx.z;
    const int cnt = g_count[e];
    const int m0  = blockIdx.y * 128;
    if (m0 >= cnt) return;
    const int n0    = blockIdx.x * 128;
    const int e_off = g_offset[e];

    const __half* Aa = (PHASE == 1) ? g_A : g_Hf;
    const __half* Be = ((PHASE == 1) ? g_W1t : g_W2t) + (size_t)e * NTOT * KTOT;

    extern __shared__ char smem[];
    const uint32_t smem_u = smem_to_u32(smem);
    const int tid  = threadIdx.x;
    const int lane = tid & 31;
    const int wid  = tid >> 5;
    const int wm   = wid >> 1;
    const int wn   = wid & 1;

    // cp.async src/dst: 4 A-chunks + 4 B-chunks per thread (128 rows x 8 chunks each)
    const __half* sA[4]; const __half* sB[4];
    uint32_t dOff[4];
#pragma unroll
    for (int i = 0; i < 4; i++) {
        int id  = tid + 256 * i;
        int row = id >> 3;
        int c   = id & 7;
        int slot = m0 + row; if (slot >= cnt) slot = cnt - 1;
        sA[i]   = Aa + (size_t)(e_off + slot) * KTOT + c * 8;
        sB[i]   = Be + (size_t)(n0 + row) * KTOT + c * 8;
        dOff[i] = row * 128 + ((c ^ (row & 7)) << 4);
    }

    // ldmatrix lane addressing (validated R5/R8/R9)
    const int a_row0 = wm * 32 + (lane & 7) + (lane & 8);
    const int a_kt   = (lane >> 4) & 1;
    const int b_row0 = wn * 64 + (lane & 7) + ((lane & 16) ? 8 : 0);
    const int b_kt   = (lane >> 3) & 1;

    float acc[2][8][4];
#pragma unroll
    for (int mb = 0; mb < 2; mb++)
#pragma unroll
        for (int nb = 0; nb < 8; nb++)
#pragma unroll
            for (int q = 0; q < 4; q++) acc[mb][nb][q] = 0.0f;

    // prologue: prefetch stages 0, 1
#pragma unroll
    for (int p = 0; p < 2; p++) {
        uint32_t st = smem_u + p * STG;
        int k0 = p * 64;
#pragma unroll
        for (int i = 0; i < 4; i++) {
            cp16(st + A_OFF + dOff[i], sA[i] + k0);
            cp16(st + B_OFF + dOff[i], sB[i] + k0);
        }
        CP_COMMIT();
    }

    int slot_c = 0;                       // ring slot of chunk c
    for (int c = 0; c < L; c++) {
        CP_WAIT1();
        __syncthreads();
        // prefetch chunk c+2 into the slot freed by chunk c-1
        if (c + 2 < L) {
            int sl = slot_c + 2; if (sl >= 3) sl -= 3;
            uint32_t st = smem_u + sl * STG;
            int k0 = (c + 2) * 64;
#pragma unroll
            for (int i = 0; i < 4; i++) {
                cp16(st + A_OFF + dOff[i], sA[i] + k0);
                cp16(st + B_OFF + dOff[i], sB[i] + k0);
            }
        }
        CP_COMMIT();

        const uint32_t st = smem_u + slot_c * STG;
#pragma unroll
        for (int ks = 0; ks < 4; ks++) {
            uint32_t aa[2][4], bb[4][4];
#pragma unroll
            for (int mb = 0; mb < 2; mb++) {
                int row = a_row0 + mb * 16;
                uint32_t off = row * 128 + (((2 * ks + a_kt) ^ (row & 7)) << 4);
                LDSM_X4(aa[mb], st + A_OFF + off);
            }
#pragma unroll
            for (int np = 0; np < 4; np++) {
                int row = b_row0 + np * 16;
                uint32_t off = row * 128 + (((2 * ks + b_kt) ^ (row & 7)) << 4);
                LDSM_X4(bb[np], st + B_OFF + off);
            }
#pragma unroll
            for (int mb = 0; mb < 2; mb++)
#pragma unroll
                for (int nb = 0; nb < 8; nb++)
                    mma_f16(acc[mb][nb], aa[mb], &bb[nb >> 1][(nb & 1) * 2]);
        }
        if (++slot_c == 3) slot_c = 0;
    }

    // epilogue
    const int gp = lane >> 2;
    const int qq = lane & 3;
#pragma unroll
    for (int mb = 0; mb < 2; mb++) {
#pragma unroll
        for (int h = 0; h < 2; h++) {
            int mloc = wm * 32 + mb * 16 + gp + h * 8;
            int slot = m0 + mloc;
            if (slot >= cnt) continue;
            if (PHASE == 1) {
                size_t hrow = (size_t)(e_off + slot) * D_FF;
#pragma unroll
                for (int nb = 0; nb < 8; nb++) {
                    int cidx = n0 + wn * 64 + nb * 8 + qq * 2;
                    float v0 = acc[mb][nb][h * 2 + 0] + __ldg(bias + e * NTOT + cidx + 0);
                    float v1 = acc[mb][nb][h * 2 + 1] + __ldg(bias + e * NTOT + cidx + 1);
                    float s0 = v0 / (1.0f + __expf(-v0));
                    float s1 = v1 / (1.0f + __expf(-v1));
                    *reinterpret_cast<uint32_t*>(g_Hf + hrow + cidx) = packf16(s0, s1);
                }
            } else {
                int   tok = g_tok[e * MAXPE + slot];
                float w   = g_wt[e * MAXPE + slot];
                float* orow = out + (size_t)tok * D_MODEL;
#pragma unroll
                for (int nb = 0; nb < 8; nb++) {
                    int cidx = n0 + wn * 64 + nb * 8 + qq * 2;
                    float v0 = acc[mb][nb][h * 2 + 0] + __ldg(bias + e * NTOT + cidx + 0);
                    float v1 = acc[mb][nb][h * 2 + 1] + __ldg(bias + e * NTOT + cidx + 1);
                    atomicAdd(orow + cidx + 0, w * v0);
                    atomicAdd(orow + cidx + 1, w * v1);
                }
            }
        }
    }
}

// ---------------------------------------------------------------------------
extern "C" void kernel_launch(void* const* d_in, const int* in_sizes, int n_in,
                              void* d_out, int out_size) {
    const float* x  = (const float*)d_in[0];
    const float* W1 = (const float*)d_in[1];
    const float* b1 = (const float*)d_in[2];
    const float* W2 = (const float*)d_in[3];
    const float* b2 = (const float*)d_in[4];
    const float* Wg = (const float*)d_in[5];
    float* out = (float*)d_out;

    cudaFuncSetAttribute(ffn_kernel<1>, cudaFuncAttributeMaxDynamicSharedMemorySize, SMEM_BYTES);
    cudaFuncSetAttribute(ffn_kernel<2>, cudaFuncAttributeMaxDynamicSharedMemorySize, SMEM_BYTES);

    reset_kernel<<<4096, 256>>>(out, out_size);
    gating_kernel<<<N_TOK / 8, 256>>>(x, Wg);
    offsets_kernel<<<1, 1>>>();
    gatherx_kernel<<<NSLOT, 128>>>(x);
    convW_kernel<1><<<dim3(D_FF / 64, D_MODEL / 64, N_EXP), 256>>>(W1);
    convW_kernel<2><<<dim3(D_MODEL / 64, D_FF / 64, N_EXP), 256>>>(W2);
    ffn_kernel<1><<<dim3(D_FF / 128, MAXPE / 128, N_EXP), 256, SMEM_BYTES>>>(b1, out);
    ffn_kernel<2><<<dim3(D_MODEL / 128, MAXPE / 128, N_EXP), 256, SMEM_BYTES>>>(b2, out);
}

// round 12
// speedup vs baseline: 6.1153x; 1.0091x over previous
#include <cuda_runtime.h>
#include <cuda_fp16.h>
#include <cstdint>
#include <math.h>

// MoE top-2/16, fp32 in/out.
// gate -> bucket -> pre-convert (x gather fp16; W transpose fp16 [e][n][k])
// -> HMMA fp16 GEMM1 (+swish, H fp16) -> HMMA GEMM2 (per-slot rows, plain stores)
// -> combine kernel (weighted sum of each token's 2 slots). No atomics anywhere.
// Mainloop (unchanged from R11): cp.async 3-stage ring + ldmatrix + mma.sync, 2 CTAs/SM.

#define D_MODEL 1024
#define N_EXP   16
#define D_FF    4096
#define N_TOK   4096
#define MAXPE   4096
#define NSLOT   (2 * N_TOK)

__device__ int    g_count[N_EXP];
__device__ int    g_offset[N_EXP + 1];
__device__ int    g_tok[N_EXP * MAXPE];
__device__ float  g_wt[N_EXP * MAXPE];
__device__ int    g_exp[N_TOK * 2];     // token -> its 2 experts
__device__ int    g_pos[N_TOK * 2];     // token -> per-expert positions
__device__ __half g_W1t[(size_t)N_EXP * D_FF * D_MODEL];   // [e][n][k]
__device__ __half g_W2t[(size_t)N_EXP * D_MODEL * D_FF];   // [e][n][k]
__device__ __half g_A[(size_t)NSLOT * D_MODEL];            // gathered x fp16
__device__ __half g_Hf[(size_t)NSLOT * D_FF];              // H fp16
__device__ float  g_O[(size_t)NSLOT * D_MODEL];            // per-slot GEMM2 out

// ---------------------------------------------------------------------------
__device__ __forceinline__ uint32_t smem_to_u32(const void* p) {
    uint32_t a;
    asm("{ .reg .u64 t; cvta.to.shared.u64 t, %1; cvt.u32.u64 %0, t; }" : "=r"(a) : "l"(p));
    return a;
}
__device__ __forceinline__ void cp16(uint32_t dst, const void* src) {
    asm volatile("cp.async.cg.shared.global [%0], [%1], 16;" :: "r"(dst), "l"(src));
}
#define CP_COMMIT() asm volatile("cp.async.commit_group;" ::: "memory")
#define CP_WAIT1()  asm volatile("cp.async.wait_group 1;" ::: "memory")

#define LDSM_X4(r, a)                                                            \
    asm volatile("ldmatrix.sync.aligned.m8n8.x4.shared.b16 {%0,%1,%2,%3}, [%4];" \
        : "=r"((r)[0]), "=r"((r)[1]), "=r"((r)[2]), "=r"((r)[3]) : "r"(a))

__device__ __forceinline__ void mma_f16(float* d, const uint32_t* a, const uint32_t* b) {
    asm volatile("mma.sync.aligned.m16n8k16.row.col.f32.f16.f16.f32 "
        "{%0,%1,%2,%3}, {%4,%5,%6,%7}, {%8,%9}, {%0,%1,%2,%3};"
        : "+f"(d[0]), "+f"(d[1]), "+f"(d[2]), "+f"(d[3])
        : "r"(a[0]), "r"(a[1]), "r"(a[2]), "r"(a[3]), "r"(b[0]), "r"(b[1]));
}

__device__ __forceinline__ uint32_t packf16(float a, float b) {
    uint32_t r;
    asm("cvt.rn.f16x2.f32 %0, %1, %2;" : "=r"(r) : "f"(b), "f"(a));
    return r;
}

// ---------------------------------------------------------------------------
// reset (16 counters) / gating / offsets
// ---------------------------------------------------------------------------
__global__ void reset_kernel() {
    if (threadIdx.x < N_EXP) g_count[threadIdx.x] = 0;
}

__global__ void gating_kernel(const float* __restrict__ x, const float* __restrict__ Wg) {
    int warp = (blockIdx.x * blockDim.x + threadIdx.x) >> 5;
    int lane = threadIdx.x & 31;
    if (warp >= N_TOK) return;
    const float* xr = x + (size_t)warp * D_MODEL;
    float acc[N_EXP];
#pragma unroll
    for (int e = 0; e < N_EXP; e++) acc[e] = 0.0f;
    for (int d = lane; d < D_MODEL; d += 32) {
        float xv = xr[d];
        const float* wr = Wg + d * N_EXP;
#pragma unroll
        for (int e = 0; e < N_EXP; e++) acc[e] = fmaf(xv, wr[e], acc[e]);
    }
#pragma unroll
    for (int e = 0; e < N_EXP; e++) {
#pragma unroll
        for (int o = 16; o > 0; o >>= 1) acc[e] += __shfl_xor_sync(0xffffffffu, acc[e], o);
    }
    if (lane == 0) {
        int i1 = 0; float v1 = acc[0];
#pragma unroll
        for (int e = 1; e < N_EXP; e++) if (acc[e] > v1) { v1 = acc[e]; i1 = e; }
        int i2 = -1; float v2 = -INFINITY;
#pragma unroll
        for (int e = 0; e < N_EXP; e++) if (e != i1 && acc[e] > v2) { v2 = acc[e]; i2 = e; }
        float e2 = expf(v2 - v1);
        float inv = 1.0f / (1.0f + e2);
        int s1 = atomicAdd(&g_count[i1], 1);
        g_tok[i1 * MAXPE + s1] = warp;  g_wt[i1 * MAXPE + s1] = inv;
        int s2 = atomicAdd(&g_count[i2], 1);
        g_tok[i2 * MAXPE + s2] = warp;  g_wt[i2 * MAXPE + s2] = e2 * inv;
        g_exp[warp * 2 + 0] = i1;  g_pos[warp * 2 + 0] = s1;
        g_exp[warp * 2 + 1] = i2;  g_pos[warp * 2 + 1] = s2;
    }
}

__global__ void offsets_kernel() {
    int s = 0;
    for (int e = 0; e < N_EXP; e++) { g_offset[e] = s; s += g_count[e]; }
    g_offset[N_EXP] = s;
}

// ---------------------------------------------------------------------------
// Pre-pass: gather x rows in expert-slot order -> fp16.
// ---------------------------------------------------------------------------
__global__ void gatherx_kernel(const float* __restrict__ x) {
    int s = blockIdx.x;
    if (s >= g_offset[N_EXP]) return;
    int e = 0;
#pragma unroll
    for (int i = 0; i < N_EXP - 1; i++) if (s >= g_offset[i + 1]) e = i + 1;
    int tok = g_tok[e * MAXPE + (s - g_offset[e])];
    const float* xr = x + (size_t)tok * D_MODEL;
    int c = threadIdx.x * 8;
    float4 a = *reinterpret_cast<const float4*>(xr + c);
    float4 b = *reinterpret_cast<const float4*>(xr + c + 4);
    uint4 o;
    o.x = packf16(a.x, a.y);
    o.y = packf16(a.z, a.w);
    o.z = packf16(b.x, b.y);
    o.w = packf16(b.z, b.w);
    *reinterpret_cast<uint4*>(g_A + (size_t)s * D_MODEL + c) = o;
}

// ---------------------------------------------------------------------------
// Pre-pass: convert+transpose weights. src [e][K][N] fp32 -> [e][N][K] fp16.
// ---------------------------------------------------------------------------
template <int WHICH>
__global__ void convW_kernel(const float* __restrict__ src) {
    constexpr int K = (WHICH == 1) ? D_MODEL : D_FF;
    constexpr int N = (WHICH == 1) ? D_FF : D_MODEL;
    __half* dstBase = (WHICH == 1) ? g_W1t : g_W2t;
    __shared__ float t[64][65];
    int e  = blockIdx.z;
    int k0 = blockIdx.y * 64;
    int n0 = blockIdx.x * 64;
    const float* S = src + (size_t)e * K * N;
    int tid = threadIdx.x;
    int rk = tid >> 4;
    int cn = (tid & 15) * 4;
#pragma unroll
    for (int p = 0; p < 4; p++) {
        float4 v = *reinterpret_cast<const float4*>(S + (size_t)(k0 + p * 16 + rk) * N + n0 + cn);
        t[p * 16 + rk][cn + 0] = v.x;
        t[p * 16 + rk][cn + 1] = v.y;
        t[p * 16 + rk][cn + 2] = v.z;
        t[p * 16 + rk][cn + 3] = v.w;
    }
    __syncthreads();
    int n  = tid >> 2;
    int kq = (tid & 3) * 16;
    uint32_t w[8];
#pragma unroll
    for (int q = 0; q < 8; q++)
        w[q] = packf16(t[kq + 2 * q][n], t[kq + 2 * q + 1][n]);
    __half* D = dstBase + (size_t)e * N * K + (size_t)(n0 + n) * K + k0 + kq;
    *reinterpret_cast<uint4*>(D)     = make_uint4(w[0], w[1], w[2], w[3]);
    *reinterpret_cast<uint4*>(D + 8) = make_uint4(w[4], w[5], w[6], w[7]);
}

// ---------------------------------------------------------------------------
// Grouped GEMM, single fp16 (mainloop identical to R11; grid: x = m-tile so
// co-scheduled CTAs share the same W slice in L2).
// ---------------------------------------------------------------------------
#define A_OFF 0
#define B_OFF 16384
#define STG   32768
#define SMEM_BYTES (3 * STG)

template <int PHASE>
__global__ __launch_bounds__(256, 2)
void ffn_kernel(const float* __restrict__ bias)
{
    constexpr int KTOT = (PHASE == 1) ? D_MODEL : D_FF;
    constexpr int NTOT = (PHASE == 1) ? D_FF : D_MODEL;
    constexpr int L    = KTOT / 64;

    const int e   = blockIdx.z;
    const int cnt = g_count[e];
    const int m0  = blockIdx.x * 128;          // m on x (adjacent CTAs share W)
    if (m0 >= cnt) return;
    const int n0    = blockIdx.y * 128;
    const int e_off = g_offset[e];

    const __half* Aa = (PHASE == 1) ? g_A : g_Hf;
    const __half* Be = ((PHASE == 1) ? g_W1t : g_W2t) + (size_t)e * NTOT * KTOT;

    extern __shared__ char smem[];
    const uint32_t smem_u = smem_to_u32(smem);
    const int tid  = threadIdx.x;
    const int lane = tid & 31;
    const int wid  = tid >> 5;
    const int wm   = wid >> 1;
    const int wn   = wid & 1;

    const __half* sA[4]; const __half* sB[4];
    uint32_t dOff[4];
#pragma unroll
    for (int i = 0; i < 4; i++) {
        int id  = tid + 256 * i;
        int row = id >> 3;
        int c   = id & 7;
        int slot = m0 + row; if (slot >= cnt) slot = cnt - 1;
        sA[i]   = Aa + (size_t)(e_off + slot) * KTOT + c * 8;
        sB[i]   = Be + (size_t)(n0 + row) * KTOT + c * 8;
        dOff[i] = row * 128 + ((c ^ (row & 7)) << 4);
    }

    const int a_row0 = wm * 32 + (lane & 7) + (lane & 8);
    const int a_kt   = (lane >> 4) & 1;
    const int b_row0 = wn * 64 + (lane & 7) + ((lane & 16) ? 8 : 0);
    const int b_kt   = (lane >> 3) & 1;

    float acc[2][8][4];
#pragma unroll
    for (int mb = 0; mb < 2; mb++)
#pragma unroll
        for (int nb = 0; nb < 8; nb++)
#pragma unroll
            for (int q = 0; q < 4; q++) acc[mb][nb][q] = 0.0f;

#pragma unroll
    for (int p = 0; p < 2; p++) {
        uint32_t st = smem_u + p * STG;
        int k0 = p * 64;
#pragma unroll
        for (int i = 0; i < 4; i++) {
            cp16(st + A_OFF + dOff[i], sA[i] + k0);
            cp16(st + B_OFF + dOff[i], sB[i] + k0);
        }
        CP_COMMIT();
    }

    int slot_c = 0;
    for (int c = 0; c < L; c++) {
        CP_WAIT1();
        __syncthreads();
        if (c + 2 < L) {
            int sl = slot_c + 2; if (sl >= 3) sl -= 3;
            uint32_t st = smem_u + sl * STG;
            int k0 = (c + 2) * 64;
#pragma unroll
            for (int i = 0; i < 4; i++) {
                cp16(st + A_OFF + dOff[i], sA[i] + k0);
                cp16(st + B_OFF + dOff[i], sB[i] + k0);
            }
        }
        CP_COMMIT();

        const uint32_t st = smem_u + slot_c * STG;
#pragma unroll
        for (int ks = 0; ks < 4; ks++) {
            uint32_t aa[2][4], bb[4][4];
#pragma unroll
            for (int mb = 0; mb < 2; mb++) {
                int row = a_row0 + mb * 16;
                uint32_t off = row * 128 + (((2 * ks + a_kt) ^ (row & 7)) << 4);
                LDSM_X4(aa[mb], st + A_OFF + off);
            }
#pragma unroll
            for (int np = 0; np < 4; np++) {
                int row = b_row0 + np * 16;
                uint32_t off = row * 128 + (((2 * ks + b_kt) ^ (row & 7)) << 4);
                LDSM_X4(bb[np], st + B_OFF + off);
            }
#pragma unroll
            for (int mb = 0; mb < 2; mb++)
#pragma unroll
                for (int nb = 0; nb < 8; nb++)
                    mma_f16(acc[mb][nb], aa[mb], &bb[nb >> 1][(nb & 1) * 2]);
        }
        if (++slot_c == 3) slot_c = 0;
    }

    // epilogue: plain stores (no atomics)
    const int gp = lane >> 2;
    const int qq = lane & 3;
#pragma unroll
    for (int mb = 0; mb < 2; mb++) {
#pragma unroll
        for (int h = 0; h < 2; h++) {
            int mloc = wm * 32 + mb * 16 + gp + h * 8;
            int slot = m0 + mloc;
            if (slot >= cnt) continue;
            if (PHASE == 1) {
                size_t hrow = (size_t)(e_off + slot) * D_FF;
#pragma unroll
                for (int nb = 0; nb < 8; nb++) {
                    int cidx = n0 + wn * 64 + nb * 8 + qq * 2;
                    float v0 = acc[mb][nb][h * 2 + 0] + __ldg(bias + e * NTOT + cidx + 0);
                    float v1 = acc[mb][nb][h * 2 + 1] + __ldg(bias + e * NTOT + cidx + 1);
                    float s0 = v0 / (1.0f + __expf(-v0));
                    float s1 = v1 / (1.0f + __expf(-v1));
                    *reinterpret_cast<uint32_t*>(g_Hf + hrow + cidx) = packf16(s0, s1);
                }
            } else {
                float* orow = g_O + (size_t)(e_off + slot) * D_MODEL;
#pragma unroll
                for (int nb = 0; nb < 8; nb++) {
                    int cidx = n0 + wn * 64 + nb * 8 + qq * 2;
                    float v0 = acc[mb][nb][h * 2 + 0] + __ldg(bias + e * NTOT + cidx + 0);
                    float v1 = acc[mb][nb][h * 2 + 1] + __ldg(bias + e * NTOT + cidx + 1);
                    float2 o; o.x = v0; o.y = v1;
                    *reinterpret_cast<float2*>(orow + cidx) = o;
                }
            }
        }
    }
}

// ---------------------------------------------------------------------------
// Combine: out[tok] = w1 * O[slot1] + w2 * O[slot2]. 4096 blocks x 256 thr,
// one float4 per thread. Writes every output element (no reset needed).
// ---------------------------------------------------------------------------
__global__ void combine_kernel(float* __restrict__ out) {
    int tok = blockIdx.x;
    int e1  = g_exp[tok * 2 + 0], e2 = g_exp[tok * 2 + 1];
    int p1  = g_pos[tok * 2 + 0], p2 = g_pos[tok * 2 + 1];
    float w1 = g_wt[e1 * MAXPE + p1];
    float w2 = g_wt[e2 * MAXPE + p2];
    const float* r1 = g_O + (size_t)(g_offset[e1] + p1) * D_MODEL;
    const float* r2 = g_O + (size_t)(g_offset[e2] + p2) * D_MODEL;
    int c = threadIdx.x * 4;
    float4 a = *reinterpret_cast<const float4*>(r1 + c);
    float4 b = *reinterpret_cast<const float4*>(r2 + c);
    float4 o;
    o.x = w1 * a.x + w2 * b.x;
    o.y = w1 * a.y + w2 * b.y;
    o.z = w1 * a.z + w2 * b.z;
    o.w = w1 * a.w + w2 * b.w;
    *reinterpret_cast<float4*>(out + (size_t)tok * D_MODEL + c) = o;
}

// ---------------------------------------------------------------------------
extern "C" void kernel_launch(void* const* d_in, const int* in_sizes, int n_in,
                              void* d_out, int out_size) {
    const float* x  = (const float*)d_in[0];
    const float* W1 = (const float*)d_in[1];
    const float* b1 = (const float*)d_in[2];
    const float* W2 = (const float*)d_in[3];
    const float* b2 = (const float*)d_in[4];
    const float* Wg = (const float*)d_in[5];
    float* out = (float*)d_out;

    cudaFuncSetAttribute(ffn_kernel<1>, cudaFuncAttributeMaxDynamicSharedMemorySize, SMEM_BYTES);
    cudaFuncSetAttribute(ffn_kernel<2>, cudaFuncAttributeMaxDynamicSharedMemorySize, SMEM_BYTES);

    reset_kernel<<<1, 32>>>();
    gating_kernel<<<N_TOK / 8, 256>>>(x, Wg);
    offsets_kernel<<<1, 1>>>();
    gatherx_kernel<<<NSLOT, 128>>>(x);
    convW_kernel<1><<<dim3(D_FF / 64, D_MODEL / 64, N_EXP), 256>>>(W1);
    convW_kernel<2><<<dim3(D_MODEL / 64, D_FF / 64, N_EXP), 256>>>(W2);
    ffn_kernel<1><<<dim3(MAXPE / 128, D_FF / 128, N_EXP), 256, SMEM_BYTES>>>(b1);
    ffn_kernel<2><<<dim3(MAXPE / 128, D_MODEL / 128, N_EXP), 256, SMEM_BYTES>>>(b2);
    combine_kernel<<<N_TOK, 256>>>(out);
}